// round 1
// baseline (speedup 1.0000x reference)
#include <cuda_runtime.h>
#include <cstdint>

// Problem constants (fixed by the dataset)
#define MROWS 8192
#define NCOLS 8192
#define KROWS 8192
#define NNZ   256
#define BATCH 32

// Intermediate bx = B @ x, [KROWS, BATCH] row-major. 1 MB device-global scratch
// (no dynamic allocation allowed).
__device__ float g_bx[KROWS * BATCH];

// One warp per output row. lane == batch column.
// Gathers src[idx*32 + lane] => one coalesced, fully-used 128B line per nnz.
// Row metadata (idx/vals) staged to smem once, read back via LDS broadcast.
// OUT_TRANSPOSED=0: dst[row*BATCH + lane]   (intermediate bx layout)
// OUT_TRANSPOSED=1: dst[lane*MROWS + row]   (final (batch, m) layout)
template<int OUT_TRANSPOSED>
__global__ void __launch_bounds__(256, 4)
ell_spmm_kernel(const int*   __restrict__ idx,
                const float* __restrict__ vals,
                const float* __restrict__ src,
                float*       __restrict__ dst)
{
    __shared__ int   s_idx[8][NNZ];
    __shared__ float s_val[8][NNZ];

    const int warp = threadIdx.x >> 5;
    const int lane = threadIdx.x & 31;
    const int row  = blockIdx.x * 8 + warp;

    // Stage this row's 256 (idx, val) pairs into smem with vector loads.
    // 256 elements / 32 lanes / 4-wide = 2 iterations.
    {
        const int4*   ip = reinterpret_cast<const int4*>(idx  + (size_t)row * NNZ);
        const float4* vp = reinterpret_cast<const float4*>(vals + (size_t)row * NNZ);
        int4*   sip = reinterpret_cast<int4*>(s_idx[warp]);
        float4* svp = reinterpret_cast<float4*>(s_val[warp]);
#pragma unroll
        for (int c = 0; c < NNZ / (32 * 4); ++c) {
            sip[c * 32 + lane] = ip[c * 32 + lane];
            svp[c * 32 + lane] = vp[c * 32 + lane];
        }
    }
    __syncwarp();

    float acc = 0.0f;
#pragma unroll 16
    for (int j = 0; j < NNZ; ++j) {
        const int   n = s_idx[warp][j];      // LDS broadcast (conflict-free)
        const float v = s_val[warp][j];
        acc += v * __ldg(&src[(size_t)n * BATCH + lane]);  // 128B coalesced gather
    }

    if (OUT_TRANSPOSED)
        dst[(size_t)lane * MROWS + row] = acc;   // out[b][m]
    else
        dst[(size_t)row * BATCH + lane] = acc;   // bx[k][b]
}

extern "C" void kernel_launch(void* const* d_in, const int* in_sizes, int n_in,
                              void* d_out, int out_size)
{
    // metadata order (== setup_inputs dict order):
    //   0: x      float32 [8192, 32]
    //   1: a_idx  int32   [8192, 256]
    //   2: a_vals float32 [8192, 256]
    //   3: b_idx  int32   [8192, 256]
    //   4: b_vals float32 [8192, 256]
    const float* x      = (const float*)d_in[0];
    const int*   a_idx  = (const int*)  d_in[1];
    const float* a_vals = (const float*)d_in[2];
    const int*   b_idx  = (const int*)  d_in[3];
    const float* b_vals = (const float*)d_in[4];
    float* out = (float*)d_out;  // (1, 32, 8192) fp32

    float* bx;
    cudaGetSymbolAddress((void**)&bx, g_bx);

    // Stage 1: bx = B @ x   (8192 rows, 8 warps/CTA -> 1024 CTAs)
    ell_spmm_kernel<0><<<KROWS / 8, 256>>>(b_idx, b_vals, x, bx);
    // Stage 2: out = (A @ bx)^T
    ell_spmm_kernel<1><<<MROWS / 8, 256>>>(a_idx, a_vals, bx, out);
}

// round 2
// speedup vs baseline: 1.2037x; 1.2037x over previous
#include <cuda_runtime.h>
#include <cstdint>

// Problem constants (fixed by the dataset)
#define MROWS 8192
#define NCOLS 8192
#define KROWS 8192
#define NNZ   256
#define BATCH 32

// Intermediate bx = B @ x, [KROWS, BATCH] row-major. 1 MB device-global scratch.
__device__ float g_bx[KROWS * BATCH];

// One warp per output row, lane == batch column.
// Metadata packed as interleaved (idx, val_bits) 8-byte pairs in smem, fetched
// two-pairs-at-a-time with LDS.128 broadcast => 0.5 L1tex wavefronts of
// metadata per nnz (vs 2 previously), plus the 1 mandatory gather wavefront.
template<int OUT_TRANSPOSED>
__global__ void __launch_bounds__(256)
ell_spmm_kernel(const int*   __restrict__ idx,
                const float* __restrict__ vals,
                const float* __restrict__ src,
                float*       __restrict__ dst)
{
    // Each uint4 holds 2 pairs: {idx0, val0_bits, idx1, val1_bits}. 2KB/warp.
    __shared__ uint4 s_pair[8][NNZ / 2];

    const int warp = threadIdx.x >> 5;
    const int lane = threadIdx.x & 31;
    const int row  = blockIdx.x * 8 + warp;

    // Stage + interleave this row's 256 (idx, val) pairs. Coalesced int4/float4
    // global loads; 2 iterations of 32 lanes x (4 idx + 4 val).
    {
        const int4*   ip = reinterpret_cast<const int4*>(idx  + (size_t)row * NNZ);
        const float4* vp = reinterpret_cast<const float4*>(vals + (size_t)row * NNZ);
#pragma unroll
        for (int c = 0; c < NNZ / (32 * 4); ++c) {
            const int4   iv = ip[c * 32 + lane];
            const float4 vv = vp[c * 32 + lane];
            uint4 p0, p1;
            p0.x = (unsigned)iv.x; p0.y = __float_as_uint(vv.x);
            p0.z = (unsigned)iv.y; p0.w = __float_as_uint(vv.y);
            p1.x = (unsigned)iv.z; p1.y = __float_as_uint(vv.z);
            p1.z = (unsigned)iv.w; p1.w = __float_as_uint(vv.w);
            const int base = (c * 32 + lane) * 2;
            s_pair[warp][base]     = p0;
            s_pair[warp][base + 1] = p1;
        }
    }
    __syncwarp();

    const float* srcl = src + lane;   // per-lane column base
    float acc = 0.0f;
#pragma unroll 8
    for (int t = 0; t < NNZ / 2; ++t) {
        const uint4 p = s_pair[warp][t];          // LDS.128 broadcast: 2 nnz/wf
        acc += __uint_as_float(p.y) * __ldg(&srcl[(size_t)p.x * BATCH]);
        acc += __uint_as_float(p.w) * __ldg(&srcl[(size_t)p.z * BATCH]);
    }

    if (OUT_TRANSPOSED)
        dst[(size_t)lane * MROWS + row] = acc;   // out[b][m]
    else
        dst[(size_t)row * BATCH + lane] = acc;   // bx[k][b]
}

extern "C" void kernel_launch(void* const* d_in, const int* in_sizes, int n_in,
                              void* d_out, int out_size)
{
    // metadata order:
    //   0: x      float32 [8192, 32]
    //   1: a_idx  int32   [8192, 256]
    //   2: a_vals float32 [8192, 256]
    //   3: b_idx  int32   [8192, 256]
    //   4: b_vals float32 [8192, 256]
    const float* x      = (const float*)d_in[0];
    const int*   a_idx  = (const int*)  d_in[1];
    const float* a_vals = (const float*)d_in[2];
    const int*   b_idx  = (const int*)  d_in[3];
    const float* b_vals = (const float*)d_in[4];
    float* out = (float*)d_out;  // (1, 32, 8192) fp32

    float* bx;
    cudaGetSymbolAddress((void**)&bx, g_bx);

    // Stage 1: bx = B @ x
    ell_spmm_kernel<0><<<KROWS / 8, 256>>>(b_idx, b_vals, x, bx);
    // Stage 2: out = (A @ bx)^T
    ell_spmm_kernel<1><<<MROWS / 8, 256>>>(a_idx, a_vals, bx, out);
}

// round 4
// speedup vs baseline: 1.5014x; 1.2474x over previous
#include <cuda_runtime.h>
#include <cstdint>

// Problem constants (fixed by the dataset)
#define MROWS 8192
#define NCOLS 8192
#define KROWS 8192
#define NNZ   256
#define BATCH 32

// Intermediate bx = B @ x, [KROWS, BATCH] row-major. 1 MB device-global scratch.
__device__ float g_bx[KROWS * BATCH];

// One warp per output row. Warp split into 4 subgroups of 8 lanes:
//   g = lane>>3  : which of 4 concurrent nnz this lane serves
//   c = lane&7   : which batch quad (batches 4c..4c+3) this lane covers
// Each gather instruction is an LDG.128 fetching 4 distinct, fully-used 128B
// lines (4 nnz at once) => LDG dispatch cost 1.82/4 = 0.455 cyc/nnz.
// Metadata: interleaved (idx, val_bits) uint2 pairs in smem; one LDS.64 with
// 4 broadcast groups serves 4 nnz per wavefront.
template<int OUT_TRANSPOSED>
__global__ void __launch_bounds__(256)
ell_spmm_kernel(const int*   __restrict__ idx,
                const float* __restrict__ vals,
                const float* __restrict__ src,
                float*       __restrict__ dst)
{
    __shared__ uint2 s_pair[8][NNZ];   // {idx, val_bits} per nnz; 2KB/warp

    const int warp = threadIdx.x >> 5;
    const int lane = threadIdx.x & 31;
    const int g    = lane >> 3;        // nnz subgroup 0..3
    const int c    = lane & 7;         // batch quad 0..7
    const int row  = blockIdx.x * 8 + warp;

    // Stage metadata: coalesced int4/float4 loads, write interleaved pairs.
    {
        const int4*   ip = reinterpret_cast<const int4*>(idx  + (size_t)row * NNZ);
        const float4* vp = reinterpret_cast<const float4*>(vals + (size_t)row * NNZ);
#pragma unroll
        for (int q = 0; q < NNZ / (32 * 4); ++q) {
            const int4   iv = ip[q * 32 + lane];
            const float4 vv = vp[q * 32 + lane];
            const int base = (q * 32 + lane) * 4;
            s_pair[warp][base + 0] = make_uint2((unsigned)iv.x, __float_as_uint(vv.x));
            s_pair[warp][base + 1] = make_uint2((unsigned)iv.y, __float_as_uint(vv.y));
            s_pair[warp][base + 2] = make_uint2((unsigned)iv.z, __float_as_uint(vv.z));
            s_pair[warp][base + 3] = make_uint2((unsigned)iv.w, __float_as_uint(vv.w));
        }
    }
    __syncwarp();

    const float4* src4 = reinterpret_cast<const float4*>(src) + c;  // lane's batch quad
    float4 acc = make_float4(0.f, 0.f, 0.f, 0.f);

#pragma unroll 4
    for (int t = 0; t < NNZ / 4; ++t) {
        const uint2  p = s_pair[warp][t * 4 + g];       // LDS.64, 4-group broadcast
        const float4 d = __ldg(&src4[(size_t)p.x * (BATCH / 4)]);  // LDG.128: 4 lines/warp
        const float  v = __uint_as_float(p.y);
        acc.x = fmaf(v, d.x, acc.x);
        acc.y = fmaf(v, d.y, acc.y);
        acc.z = fmaf(v, d.z, acc.z);
        acc.w = fmaf(v, d.w, acc.w);
    }

    // Reduce partial sums across the 4 nnz subgroups (lanes 8 apart share c).
#pragma unroll
    for (int off = 8; off < 32; off <<= 1) {
        acc.x += __shfl_xor_sync(0xffffffffu, acc.x, off);
        acc.y += __shfl_xor_sync(0xffffffffu, acc.y, off);
        acc.z += __shfl_xor_sync(0xffffffffu, acc.z, off);
        acc.w += __shfl_xor_sync(0xffffffffu, acc.w, off);
    }

    if (g == 0) {  // lanes 0..7 hold the full row result for batches 4c..4c+3
        if (OUT_TRANSPOSED) {
            dst[(size_t)(4 * c + 0) * MROWS + row] = acc.x;
            dst[(size_t)(4 * c + 1) * MROWS + row] = acc.y;
            dst[(size_t)(4 * c + 2) * MROWS + row] = acc.z;
            dst[(size_t)(4 * c + 3) * MROWS + row] = acc.w;
        } else {
            reinterpret_cast<float4*>(dst + (size_t)row * BATCH)[c] = acc;  // STG.128 coalesced
        }
    }
}

extern "C" void kernel_launch(void* const* d_in, const int* in_sizes, int n_in,
                              void* d_out, int out_size)
{
    // metadata order:
    //   0: x      float32 [8192, 32]
    //   1: a_idx  int32   [8192, 256]
    //   2: a_vals float32 [8192, 256]
    //   3: b_idx  int32   [8192, 256]
    //   4: b_vals float32 [8192, 256]
    const float* x      = (const float*)d_in[0];
    const int*   a_idx  = (const int*)  d_in[1];
    const float* a_vals = (const float*)d_in[2];
    const int*   b_idx  = (const int*)  d_in[3];
    const float* b_vals = (const float*)d_in[4];
    float* out = (float*)d_out;  // (1, 32, 8192) fp32

    float* bx;
    cudaGetSymbolAddress((void**)&bx, g_bx);

    // Stage 1: bx = B @ x
    ell_spmm_kernel<0><<<KROWS / 8, 256>>>(b_idx, b_vals, x, bx);
    // Stage 2: out = (A @ bx)^T
    ell_spmm_kernel<1><<<MROWS / 8, 256>>>(a_idx, a_vals, bx, out);
}